// round 13
// baseline (speedup 1.0000x reference)
#include <cuda_runtime.h>

#define NBANDS 31
#define NB     16
#define NT     1000
#define NF     257
#define NO     128
#define MAXC   34
#define KTOT   536      // sum of roundup4(2*bw)
#define TT     8        // time tile per block
#define NCH    8        // stats chunks per (b,band)
#define OUTW   (NO * NBANDS)   // 3968
#define OHW    (64 * NBANDS)   // 1984 floats per (t, o-half)

__constant__ int c_bw[NBANDS] = {
    2,3,3,3,3,3,3,3,3,3,3,
    8,8,8,8,8,8,8,8,8,8,8,8,
    16,16,16,16,16,16,16,17
};
__constant__ int c_kal[NBANDS] = {
    0,4,12,20,28,36,44,52,60,68,76,
    84,100,116,132,148,164,180,196,212,228,244,260,
    276,308,340,372,404,436,468,500
};
__constant__ int c_f0[NBANDS] = {
    0,2,5,8,11,14,17,20,23,26,29,
    32,40,48,56,64,72,80,88,96,104,112,120,
    128,144,160,176,192,208,224,240
};
// 16 band-groups (one warp each)
__constant__ int c_gs[17] = {0,1,2,3,4,5,6,7,8,10,12,14,16,18,21,26,31};
__constant__ int c_gb[31] = {
    30,
    23,24,25,26,27,28,29,
    11,12, 13,14, 15,16, 17,18, 19,20,
    21,22,0,
    1,2,3,4,5,
    6,7,8,9,10
};
// group-contiguous weight layout: per-band offset (in k-slots) inside d_w3
__constant__ int c_wof[NBANDS] = {
    452,                                  // band 0 (in group 13)
    456,464,472,480,488,                  // bands 1-5  (group 14)
    496,504,512,520,528,                  // bands 6-10 (group 15)
    260,276, 292,308, 324,340, 356,372, 388,404,   // bands 11-20 (groups 8-12)
    420,436,                              // bands 21,22 (group 13)
    36,68,100,132,164,196,228,            // bands 23-29 (groups 1-7)
    0                                     // band 30 (group 0)
};
// group chunk starts (k-slots), 17 entries
__constant__ int c_goff[17] = {
    0,36,68,100,132,164,196,228,260,292,324,356,388,420,456,496,536
};
// k-slots that are zero-padding (kal-space, for s_y)
__constant__ int c_pad[22] = {
    10,11,18,19,26,27,34,35,42,43,50,51,58,59,66,67,74,75,82,83,534,535
};

// static scratch
__device__ float  d_A2[NB * KTOT];
__device__ float  d_B2[NB * KTOT];
// group-ordered per-half weights: [h][wof+k][64], pos 2l+s holds o = h*64+l+32s
__device__ __align__(128) float d_w3[2 * KTOT * 64];
__device__ float  d_bp[NBANDS * NO];          // interleaved-o bias
__device__ float2 d_ps[NB * NBANDS * NCH];    // partial (sum, sumsq)

__device__ __forceinline__ int kg_of_f(int f)
{
    if (f >= 32) return 2 * f + 20;
    if (f >= 2)  return 2 * f - 2 + 2 * ((f + 1) / 3);
    return 2 * f;
}

__device__ __forceinline__ float2 u2f(unsigned long long u)
{
    float2 r;
    asm("mov.b64 {%0,%1}, %2;" : "=f"(r.x), "=f"(r.y) : "l"(u));
    return r;
}
__device__ __forceinline__ unsigned long long dupf(float f)
{
    unsigned long long r;
    asm("mov.b64 %0, {%1, %1};" : "=l"(r) : "f"(f));
    return r;
}

// ---------------------------------------------------------------------------
// Stats stage 1: partial sums over a t-chunk of x[b, f0:f0+bw, :, :]
// ---------------------------------------------------------------------------
__global__ __launch_bounds__(256)
void stats1(const float* __restrict__ x)
{
    const int b    = blockIdx.x;
    const int band = blockIdx.y;
    const int ch   = blockIdx.z;
    const int bw   = c_bw[band];
    const float4* p = (const float4*)(x + (size_t)(b * NF + c_f0[band]) * (NT * 2));
    const int nv = bw * NT / 2;
    const int i0 = (int)((long long)nv * ch / NCH);
    const int i1 = (int)((long long)nv * (ch + 1) / NCH);

    float4 a1 = make_float4(0.f, 0.f, 0.f, 0.f);
    float4 a2 = a1;
    for (int i = i0 + threadIdx.x; i < i1; i += 256) {
        float4 v = p[i];
        a1.x += v.x; a1.y += v.y; a1.z += v.z; a1.w += v.w;
        a2.x = fmaf(v.x, v.x, a2.x); a2.y = fmaf(v.y, v.y, a2.y);
        a2.z = fmaf(v.z, v.z, a2.z); a2.w = fmaf(v.w, v.w, a2.w);
    }
    float s  = (a1.x + a1.y) + (a1.z + a1.w);
    float s2 = (a2.x + a2.y) + (a2.z + a2.w);
    for (int off = 16; off; off >>= 1) {
        s  += __shfl_down_sync(0xFFFFFFFFu, s,  off);
        s2 += __shfl_down_sync(0xFFFFFFFFu, s2, off);
    }
    __shared__ float sh0[8], sh1[8];
    const int w = threadIdx.x >> 5, l = threadIdx.x & 31;
    if (l == 0) { sh0[w] = s; sh1[w] = s2; }
    __syncthreads();
    if (threadIdx.x == 0) {
        float ts = 0.f, ts2 = 0.f;
        #pragma unroll
        for (int i = 0; i < 8; i++) { ts += sh0[i]; ts2 += sh1[i]; }
        d_ps[(b * NBANDS + band) * NCH + ch] = make_float2(ts, ts2);
    }
}

// ---------------------------------------------------------------------------
// Stage 2 merged: y < NB -> stats finalize; y == NB -> weight/bias prep.
// ---------------------------------------------------------------------------
__global__ __launch_bounds__(256)
void stats2_prep(const float* __restrict__ gnw, const float* __restrict__ gnb,
                 const float* __restrict__ fcw, const float* __restrict__ fcb)
{
    const int band = blockIdx.x;
    const int bw   = c_bw[band];
    const int kal  = c_kal[band];

    if (blockIdx.y < NB) {
        const int b = blockIdx.y;
        const int n = bw * NT * 2;
        __shared__ float sh_mean, sh_inv;
        if (threadIdx.x == 0) {
            double ts = 0.0, ts2 = 0.0;
            #pragma unroll
            for (int i = 0; i < NCH; i++) {
                float2 v = d_ps[(b * NBANDS + band) * NCH + i];
                ts += (double)v.x; ts2 += (double)v.y;
            }
            double mean = ts / n;
            double var  = ts2 / n - mean * mean;
            sh_mean = (float)mean;
            sh_inv  = rsqrtf((float)var + 1e-5f);
        }
        __syncthreads();
        const int c = 2 * bw;
        if (threadIdx.x < c) {
            float gw = gnw[band * MAXC + threadIdx.x];
            float gb = gnb[band * MAXC + threadIdx.x];
            float A  = gw * sh_inv;
            d_A2[b * KTOT + kal + threadIdx.x] = A;
            d_B2[b * KTOT + kal + threadIdx.x] = gb - A * sh_mean;
        }
    } else {
        // group-ordered per-half weights: d_w3[h][wof+k][2l+s] = w[o=h*64+l+32s]
        const int C   = 2 * bw;
        const int kp  = (C + 3) & ~3;
        const int wof = c_wof[band];
        for (int idx = threadIdx.x; idx < kp * NO; idx += 256) {
            const int k = idx >> 7;
            const int p = idx & 127;
            const int h = p >> 6;
            const int r = p & 63;
            const int l = r >> 1;
            const int s = r & 1;
            const int o = h * 64 + l + 32 * s;
            d_w3[(h * KTOT + wof + k) * 64 + 2 * l + s] =
                (k < C) ? fcw[(band * NO + o) * MAXC + k] : 0.0f;
        }
        if (threadIdx.x < NO) {
            const int p = threadIdx.x;
            const int h = p >> 6;
            const int r = p & 63;
            const int l = r >> 1;
            const int s = r & 1;
            d_bp[band * NO + p] = fcb[band * NO + h * 64 + l + 32 * s];
        }
    }
}

// ---------------------------------------------------------------------------
// Fused kernel, occ 1 + weights in smem. 16 per-group cp.async.bulk weight
// loads (own mbarrier each) issued before y-build; warp w waits only on its
// chunk, then runs the gemm entirely from smem (zero global latency in the
// k-loop). Staging + TMA bulk store as R10.
// ---------------------------------------------------------------------------
#define MB_F     32                           // 16 mbarriers (u64)
#define SW_F     (KTOT * 64)                  // 34304 floats (137216 B)
#define SOUT_F   (TT * OHW)                   // 15872 floats
#define SY_F     (KTOT * TT)                  // 4288 floats
#define SMEM_F   (MB_F + SW_F + SOUT_F + SY_F + 2 * KTOT)  // 55568 fl = 222272 B

#define FMA2(acc, wv, yv) \
    asm("fma.rn.f32x2 %0, %1, %2, %0;" : "+l"(acc) : "l"(wv), "l"(yv));

__global__ __launch_bounds__(512, 1)
void fused_kernel(const float* __restrict__ x,
                  float* __restrict__ out)
{
    extern __shared__ float sm[];
    float* s_w   = sm + MB_F;                 // [gslot][64], group-ordered
    float* s_out = s_w + SW_F;                // [t][OHW] exact output order
    float* s_y   = s_out + SOUT_F;            // [k][8]
    float* s_A   = s_y + SY_F;
    float* s_B   = s_A + KTOT;

    const int b    = blockIdx.y;
    const int t0   = blockIdx.x * TT;
    const int h    = blockIdx.z;              // o-half
    const int tid  = threadIdx.x;
    const int lane = tid & 31;
    const int warp = tid >> 5;                // band group

    unsigned int smbase;
    asm("{ .reg .u64 t; cvta.to.shared.u64 t, %1; cvt.u32.u64 %0, t; }"
        : "=r"(smbase) : "l"(sm));
    const unsigned int mb_base = smbase;             // 16 x u64
    const unsigned int sw_addr = smbase + MB_F * 4;

    // init 16 mbarriers, then issue the 16 weight chunk loads
    if (tid < 16) {
        asm volatile("mbarrier.init.shared.b64 [%0], %1;"
                     :: "r"(mb_base + tid * 8), "r"(1) : "memory");
    }
    __syncthreads();
    if (tid < 16) {
        const int g0 = c_goff[tid];
        const unsigned int bytes = (unsigned int)(c_goff[tid + 1] - g0) * 256u;
        const unsigned int dst = sw_addr + (unsigned int)g0 * 256u;
        const char* src = (const char*)d_w3 + ((size_t)h * KTOT + g0) * 256;
        const unsigned int mb = mb_base + tid * 8;
        asm volatile("mbarrier.arrive.expect_tx.shared.b64 _, [%0], %1;"
                     :: "r"(mb), "r"(bytes) : "memory");
        asm volatile("cp.async.bulk.shared::cta.global.mbarrier::complete_tx::bytes "
                     "[%0], [%1], %2, [%3];"
                     :: "r"(dst), "l"(src), "r"(bytes), "r"(mb) : "memory");
    }

    // bias prefetch for first band (global, tiny)
    int bi          = c_gs[warp];
    const int biEnd = c_gs[warp + 1];
    int band = c_gb[bi];
    unsigned long long bz =
        *((const unsigned long long*)(d_bp + band * NO + h * 64) + lane);

    for (int i = tid; i < KTOT; i += 512) {
        s_A[i] = d_A2[b * KTOT + i];
        s_B[i] = d_B2[b * KTOT + i];
    }
    // zero the 22 padded k-slots (all 8 t's each)
    if (tid < 22 * TT) {
        const int slot = c_pad[tid >> 3];
        s_y[slot * TT + (tid & 7)] = 0.0f;
    }
    __syncthreads();

    // y-build: s_y[kg][t] = A*x + B (weight TMA streams in underneath)
    for (int idx = tid; idx < NF * 4; idx += 512) {
        const int f = idx >> 2;
        const int q = idx & 3;                // t-pair q: t = t0+2q, t0+2q+1
        const float4 v = *(const float4*)(x + ((size_t)(b * NF + f) * NT + t0) * 2 + q * 4);
        const int kg = kg_of_f(f);
        const float A0 = s_A[kg], B0 = s_B[kg];
        const float A1 = s_A[kg + 1], B1 = s_B[kg + 1];
        *(float2*)&s_y[kg * TT + 2 * q] =
            make_float2(fmaf(A0, v.x, B0), fmaf(A0, v.z, B0));
        *(float2*)&s_y[(kg + 1) * TT + 2 * q] =
            make_float2(fmaf(A1, v.y, B1), fmaf(A1, v.w, B1));
    }
    __syncthreads();

    // wait ONLY for this warp's weight chunk (acquire)
    {
        const unsigned int mb = mb_base + warp * 8;
        unsigned int done;
        do {
            asm volatile(
                "{\n\t.reg .pred p;\n\t"
                "mbarrier.try_wait.parity.acquire.cta.shared::cta.b64 p, [%1], %2, 0x989680;\n\t"
                "selp.b32 %0, 1, 0, p;\n\t}"
                : "=r"(done) : "r"(mb), "r"(0u) : "memory");
        } while (!done);
    }

    // --- band loop: gemm entirely from smem
    for (;;) {
        const int kcnt = (2 * c_bw[band] + 3) & ~3;
        const float* yb = s_y + c_kal[band] * TT;
        const unsigned long long* wrow =
            (const unsigned long long*)(s_w + c_wof[band] * 64) + lane;

        unsigned long long acc[4][2];   // [t-pair][oA/oB]
        {
            float2 bf = u2f(bz);
            unsigned long long bA = dupf(bf.x), bB = dupf(bf.y);
            #pragma unroll
            for (int tp = 0; tp < 4; tp++) { acc[tp][0] = bA; acc[tp][1] = bB; }
        }

        #pragma unroll 4
        for (int k = 0; k < kcnt; k++) {
            const unsigned long long w = wrow[k * 32];          // LDS.64, conflict-free
            float2 wf = u2f(w);
            const unsigned long long wA = dupf(wf.x);
            const unsigned long long wB = dupf(wf.y);
            const ulonglong2 y01 = *(const ulonglong2*)(yb + k * TT);      // broadcast
            const ulonglong2 y23 = *(const ulonglong2*)(yb + k * TT + 4);
            FMA2(acc[0][0], wA, y01.x) FMA2(acc[0][1], wB, y01.x)
            FMA2(acc[1][0], wA, y01.y) FMA2(acc[1][1], wB, y01.y)
            FMA2(acc[2][0], wA, y23.x) FMA2(acc[2][1], wB, y23.x)
            FMA2(acc[3][0], wA, y23.y) FMA2(acc[3][1], wB, y23.y)
        }

        // next band bias prefetch before staging
        const int curBand = band;
        const bool more = (++bi < biEnd);
        if (more) {
            band = c_gb[bi];
            bz = *((const unsigned long long*)(d_bp + band * NO + h * 64) + lane);
        }

        // conflict-free staging: addr = 31*lane + band (+992 for o+32);
        // strides (OHW=1984, 992) are 0 mod 32
        #pragma unroll
        for (int tp = 0; tp < 4; tp++) {
            float* so = s_out + (2 * tp) * OHW + 31 * lane + curBand;
            float2 pa = u2f(acc[tp][0]);    // o = h*64 + lane,    t / t+1
            float2 pb = u2f(acc[tp][1]);    // o = h*64 + lane+32
            so[0]         = pa.x;
            so[OHW]       = pa.y;
            so[992]       = pb.x;
            so[OHW + 992] = pb.y;
        }
        if (!more) break;
    }
    __syncthreads();

    // per-t contiguous bulk stores: 7936 B each (o-half slab is contiguous)
    if (tid == 0) {
        const unsigned int so_addr = sw_addr + SW_F * 4;
        asm volatile("fence.proxy.async.shared::cta;" ::: "memory");
        #pragma unroll
        for (int t = 0; t < TT; t++) {
            float* dst = out + (size_t)(b * NT + t0 + t) * OUTW + h * OHW;
            asm volatile("cp.async.bulk.global.shared::cta.bulk_group [%0], [%1], %2;"
                         :: "l"(dst), "r"(so_addr + t * (OHW * 4)), "n"(OHW * 4)
                         : "memory");
        }
        asm volatile("cp.async.bulk.commit_group;" ::: "memory");
        asm volatile("cp.async.bulk.wait_group.read 0;" ::: "memory");
    }
}

// ---------------------------------------------------------------------------
extern "C" void kernel_launch(void* const* d_in, const int* in_sizes, int n_in,
                              void* d_out, int out_size)
{
    const float* x   = (const float*)d_in[0];
    const float* gnw = (const float*)d_in[1];
    const float* gnb = (const float*)d_in[2];
    const float* fcw = (const float*)d_in[3];
    const float* fcb = (const float*)d_in[4];
    float* out = (float*)d_out;

    const int smem_bytes = SMEM_F * 4;        // 222272 B
    cudaFuncSetAttribute(fused_kernel,
                         cudaFuncAttributeMaxDynamicSharedMemorySize, smem_bytes);

    stats1<<<dim3(NB, NBANDS, NCH), 256>>>(x);
    stats2_prep<<<dim3(NBANDS, NB + 1), 256>>>(gnw, gnb, fcw, fcb);
    fused_kernel<<<dim3(NT / TT, NB, 2), 512, smem_bytes>>>(x, out);
}

// round 14
// speedup vs baseline: 1.4678x; 1.4678x over previous
#include <cuda_runtime.h>

#define NBANDS 31
#define NB     16
#define NT     1000
#define NF     257
#define NO     128
#define MAXC   34
#define KTOT   536      // sum of roundup4(2*bw)
#define TT     10       // time tile per block
#define YS     12       // y row stride (floats, 48B: keeps 16B alignment)
#define NCH    8        // stats chunks per (b,band)
#define OUTW   (NO * NBANDS)   // 3968
#define OHW    (64 * NBANDS)   // 1984 floats per (t, o-half)

__constant__ int c_bw[NBANDS] = {
    2,3,3,3,3,3,3,3,3,3,3,
    8,8,8,8,8,8,8,8,8,8,8,8,
    16,16,16,16,16,16,16,17
};
__constant__ int c_kal[NBANDS] = {
    0,4,12,20,28,36,44,52,60,68,76,
    84,100,116,132,148,164,180,196,212,228,244,260,
    276,308,340,372,404,436,468,500
};
__constant__ int c_f0[NBANDS] = {
    0,2,5,8,11,14,17,20,23,26,29,
    32,40,48,56,64,72,80,88,96,104,112,120,
    128,144,160,176,192,208,224,240
};
// 16 band-groups (one warp each); padded-C sums 32..44
__constant__ int c_gs[17] = {0,1,2,3,4,5,6,7,8,10,12,14,16,18,21,26,31};
__constant__ int c_gb[31] = {
    30,
    23,24,25,26,27,28,29,
    11,12, 13,14, 15,16, 17,18, 19,20,
    21,22,0,
    1,2,3,4,5,
    6,7,8,9,10
};
// k-slots that are zero-padding
__constant__ int c_pad[22] = {
    10,11,18,19,26,27,34,35,42,43,50,51,58,59,66,67,74,75,82,83,534,535
};

// static scratch
__device__ float  d_A2[NB * KTOT];
__device__ float  d_B2[NB * KTOT];
// per-half weights: [h][kslot][64], pos 2l+s holds o = h*64 + l + 32*s
__device__ float  d_w2h[2 * KTOT * 64];
// bias, same per-half pairing: [band][h][64]
__device__ float  d_bp[NBANDS * NO];
__device__ float2 d_ps[NB * NBANDS * NCH];    // partial (sum, sumsq)

__device__ __forceinline__ int kg_of_f(int f)
{
    if (f >= 32) return 2 * f + 20;
    if (f >= 2)  return 2 * f - 2 + 2 * ((f + 1) / 3);
    return 2 * f;
}

__device__ __forceinline__ float2 u2f(unsigned long long u)
{
    float2 r;
    asm("mov.b64 {%0,%1}, %2;" : "=f"(r.x), "=f"(r.y) : "l"(u));
    return r;
}
__device__ __forceinline__ unsigned long long dupf(float f)
{
    unsigned long long r;
    asm("mov.b64 %0, {%1, %1};" : "=l"(r) : "f"(f));
    return r;
}

// ---------------------------------------------------------------------------
// Stats stage 1: partial sums over a t-chunk of x[b, f0:f0+bw, :, :]
// ---------------------------------------------------------------------------
__global__ __launch_bounds__(256)
void stats1(const float* __restrict__ x)
{
    const int b    = blockIdx.x;
    const int band = blockIdx.y;
    const int ch   = blockIdx.z;
    const int bw   = c_bw[band];
    const float4* p = (const float4*)(x + (size_t)(b * NF + c_f0[band]) * (NT * 2));
    const int nv = bw * NT / 2;
    const int i0 = (int)((long long)nv * ch / NCH);
    const int i1 = (int)((long long)nv * (ch + 1) / NCH);

    float4 a1 = make_float4(0.f, 0.f, 0.f, 0.f);
    float4 a2 = a1;
    for (int i = i0 + threadIdx.x; i < i1; i += 256) {
        float4 v = p[i];
        a1.x += v.x; a1.y += v.y; a1.z += v.z; a1.w += v.w;
        a2.x = fmaf(v.x, v.x, a2.x); a2.y = fmaf(v.y, v.y, a2.y);
        a2.z = fmaf(v.z, v.z, a2.z); a2.w = fmaf(v.w, v.w, a2.w);
    }
    float s  = (a1.x + a1.y) + (a1.z + a1.w);
    float s2 = (a2.x + a2.y) + (a2.z + a2.w);
    for (int off = 16; off; off >>= 1) {
        s  += __shfl_down_sync(0xFFFFFFFFu, s,  off);
        s2 += __shfl_down_sync(0xFFFFFFFFu, s2, off);
    }
    __shared__ float sh0[8], sh1[8];
    const int w = threadIdx.x >> 5, l = threadIdx.x & 31;
    if (l == 0) { sh0[w] = s; sh1[w] = s2; }
    __syncthreads();
    if (threadIdx.x == 0) {
        float ts = 0.f, ts2 = 0.f;
        #pragma unroll
        for (int i = 0; i < 8; i++) { ts += sh0[i]; ts2 += sh1[i]; }
        d_ps[(b * NBANDS + band) * NCH + ch] = make_float2(ts, ts2);
    }
}

// ---------------------------------------------------------------------------
// Stage 2 merged: y < NB -> stats finalize; y == NB -> weight/bias prep.
// ---------------------------------------------------------------------------
__global__ __launch_bounds__(256)
void stats2_prep(const float* __restrict__ gnw, const float* __restrict__ gnb,
                 const float* __restrict__ fcw, const float* __restrict__ fcb)
{
    const int band = blockIdx.x;
    const int bw   = c_bw[band];
    const int kal  = c_kal[band];

    if (blockIdx.y < NB) {
        const int b = blockIdx.y;
        const int n = bw * NT * 2;
        __shared__ float sh_mean, sh_inv;
        if (threadIdx.x == 0) {
            double ts = 0.0, ts2 = 0.0;
            #pragma unroll
            for (int i = 0; i < NCH; i++) {
                float2 v = d_ps[(b * NBANDS + band) * NCH + i];
                ts += (double)v.x; ts2 += (double)v.y;
            }
            double mean = ts / n;
            double var  = ts2 / n - mean * mean;
            sh_mean = (float)mean;
            sh_inv  = rsqrtf((float)var + 1e-5f);
        }
        __syncthreads();
        const int c = 2 * bw;
        if (threadIdx.x < c) {
            float gw = gnw[band * MAXC + threadIdx.x];
            float gb = gnb[band * MAXC + threadIdx.x];
            float A  = gw * sh_inv;
            d_A2[b * KTOT + kal + threadIdx.x] = A;
            d_B2[b * KTOT + kal + threadIdx.x] = gb - A * sh_mean;
        }
    } else {
        // per-half weight prep: d_w2h[h][kal+k][2l+s] = w[o = h*64+l+32s]
        const int C  = 2 * bw;
        const int kp = (C + 3) & ~3;
        for (int idx = threadIdx.x; idx < kp * NO; idx += 256) {
            const int k = idx >> 7;
            const int p = idx & 127;
            const int h = p >> 6;
            const int r = p & 63;
            const int l = r >> 1;
            const int s = r & 1;
            const int o = h * 64 + l + 32 * s;
            d_w2h[(h * KTOT + kal + k) * 64 + 2 * l + s] =
                (k < C) ? fcw[(band * NO + o) * MAXC + k] : 0.0f;
        }
        if (threadIdx.x < NO) {
            const int p = threadIdx.x;
            const int h = p >> 6;
            const int r = p & 63;
            const int l = r >> 1;
            const int s = r & 1;
            d_bp[band * NO + p] = fcb[band * NO + h * 64 + l + 32 * s];
        }
    }
}

// ---------------------------------------------------------------------------
// Fused kernel: block = (10-t tile, batch, o-half), occ 2. t-pair f32x2
// packing: acc = {out[t],out[t+1]} x 5 pairs; y rows padded to 12 floats so
// broadcast LDS.128 stays aligned. Depth-4 weight pipeline; conflict-free
// staging; 10 contiguous TMA bulk stores.
// ---------------------------------------------------------------------------
#define SOUT_F   (TT * OHW)                   // 19840 floats (79360 B)
#define SY_F     (KTOT * YS)                  // 6432 floats  (25728 B)
#define SMEM_F   (SOUT_F + SY_F + 2 * KTOT)   // 27344 floats = 109376 B

#define FMA2(acc, wv, yv) \
    asm("fma.rn.f32x2 %0, %1, %2, %0;" : "+l"(acc) : "l"(wv), "l"(yv));

__global__ __launch_bounds__(512, 2)
void fused_kernel(const float* __restrict__ x,
                  float* __restrict__ out)
{
    extern __shared__ float sm[];
    float* s_out = sm;                        // [t][OHW] exact output order
    float* s_y   = sm + SOUT_F;               // [k][YS] (10 valid floats/row)
    float* s_A   = sm + SOUT_F + SY_F;
    float* s_B   = s_A + KTOT;

    const int b    = blockIdx.y;
    const int t0   = blockIdx.x * TT;
    const int h    = blockIdx.z;              // o-half
    const int tid  = threadIdx.x;
    const int lane = tid & 31;
    const int warp = tid >> 5;                // band group

    const unsigned long long* wbase =
        (const unsigned long long*)d_w2h + (size_t)h * KTOT * 32;

    // --- prefetch first band's bias + first 4 weight rows (hidden by y-build)
    int bi          = c_gs[warp];
    const int biEnd = c_gs[warp + 1];
    int band = c_gb[bi];
    int kal  = c_kal[band];
    unsigned long long bz =
        *((const unsigned long long*)(d_bp + band * NO + h * 64) + lane);
    const unsigned long long* wp = wbase + kal * 32 + lane;
    unsigned long long wq0 = wp[0];
    unsigned long long wq1 = wp[32];
    unsigned long long wq2 = wp[64];
    unsigned long long wq3 = wp[96];

    for (int i = tid; i < KTOT; i += 512) {
        s_A[i] = d_A2[b * KTOT + i];
        s_B[i] = d_B2[b * KTOT + i];
    }
    // zero the 22 padded k-slots (first 10 floats of each row)
    if (tid < 220) {
        const int slot = c_pad[tid / 10];
        s_y[slot * YS + (tid % 10)] = 0.0f;
    }
    __syncthreads();

    // y-build: s_y[kg][t] = A*x + B; float4 covers (t,t+1)x(re,im) -> 2 STS.64
    for (int idx = tid; idx < NF * 5; idx += 512) {
        const int f = idx / 5;
        const int q = idx - 5 * f;            // t-pair q: t = t0+2q, t0+2q+1
        const float4 v = *(const float4*)(x + ((size_t)(b * NF + f) * NT + t0) * 2 + q * 4);
        const int kg = kg_of_f(f);
        const float A0 = s_A[kg], B0 = s_B[kg];
        const float A1 = s_A[kg + 1], B1 = s_B[kg + 1];
        *(float2*)&s_y[kg * YS + 2 * q] =
            make_float2(fmaf(A0, v.x, B0), fmaf(A0, v.z, B0));
        *(float2*)&s_y[(kg + 1) * YS + 2 * q] =
            make_float2(fmaf(A1, v.y, B1), fmaf(A1, v.w, B1));
    }
    __syncthreads();

    // --- band loop, depth-4 pipelined weight stream
    for (;;) {
        const int kcnt = (2 * c_bw[band] + 3) & ~3;
        const float* yb = s_y + kal * YS;

        unsigned long long acc[5][2];   // [t-pair][oA/oB]
        {
            float2 bf = u2f(bz);
            unsigned long long bA = dupf(bf.x), bB = dupf(bf.y);
            #pragma unroll
            for (int tp = 0; tp < 5; tp++) { acc[tp][0] = bA; acc[tp][1] = bB; }
        }

        #pragma unroll 4
        for (int k = 0; k < kcnt; k++) {
            const unsigned long long w = wq0;
            wq0 = wq1; wq1 = wq2; wq2 = wq3;
            const int kn = (k + 4 < kcnt) ? k + 4 : k;   // clamp (L1 hit on reload)
            wq3 = wp[kn * 32];

            float2 wf = u2f(w);
            const unsigned long long wA = dupf(wf.x);
            const unsigned long long wB = dupf(wf.y);

            // y row: 10 floats, 16B-aligned (YS=12) -> 2x LDS.128 + 1x LDS.64
            const ulonglong2 y01 = *(const ulonglong2*)(yb + k * YS);      // pairs 0,1
            const ulonglong2 y23 = *(const ulonglong2*)(yb + k * YS + 4);  // pairs 2,3
            const unsigned long long y4 =
                *(const unsigned long long*)(yb + k * YS + 8);             // pair 4
            FMA2(acc[0][0], wA, y01.x) FMA2(acc[0][1], wB, y01.x)
            FMA2(acc[1][0], wA, y01.y) FMA2(acc[1][1], wB, y01.y)
            FMA2(acc[2][0], wA, y23.x) FMA2(acc[2][1], wB, y23.x)
            FMA2(acc[3][0], wA, y23.y) FMA2(acc[3][1], wB, y23.y)
            FMA2(acc[4][0], wA, y4)    FMA2(acc[4][1], wB, y4)
        }

        // prefetch next band before staging stores
        const int curBand = band;
        const bool more = (++bi < biEnd);
        if (more) {
            band = c_gb[bi];
            kal  = c_kal[band];
            wp   = wbase + kal * 32 + lane;
            bz   = *((const unsigned long long*)(d_bp + band * NO + h * 64) + lane);
            wq0 = wp[0]; wq1 = wp[32]; wq2 = wp[64]; wq3 = wp[96];
        }

        // conflict-free staging: addr = 31*lane + band (+992 for o+32);
        // strides (OHW=1984, 992) are 0 mod 32
        #pragma unroll
        for (int tp = 0; tp < 5; tp++) {
            float* so = s_out + (2 * tp) * OHW + 31 * lane + curBand;
            float2 pa = u2f(acc[tp][0]);    // o = h*64 + lane,    t / t+1
            float2 pb = u2f(acc[tp][1]);    // o = h*64 + lane+32
            so[0]         = pa.x;
            so[OHW]       = pa.y;
            so[992]       = pb.x;
            so[OHW + 992] = pb.y;
        }
        if (!more) break;
    }
    __syncthreads();

    // per-t contiguous bulk copies: 7936 B each (o-half slab is contiguous)
    if (tid == 0) {
        unsigned int saddr;
        asm("{ .reg .u64 t; cvta.to.shared.u64 t, %1; cvt.u32.u64 %0, t; }"
            : "=r"(saddr) : "l"(s_out));
        asm volatile("fence.proxy.async.shared::cta;" ::: "memory");
        #pragma unroll
        for (int t = 0; t < TT; t++) {
            float* dst = out + (size_t)(b * NT + t0 + t) * OUTW + h * OHW;
            asm volatile("cp.async.bulk.global.shared::cta.bulk_group [%0], [%1], %2;"
                         :: "l"(dst), "r"(saddr + t * (OHW * 4)), "n"(OHW * 4)
                         : "memory");
        }
        asm volatile("cp.async.bulk.commit_group;" ::: "memory");
        asm volatile("cp.async.bulk.wait_group.read 0;" ::: "memory");
    }
}

// ---------------------------------------------------------------------------
extern "C" void kernel_launch(void* const* d_in, const int* in_sizes, int n_in,
                              void* d_out, int out_size)
{
    const float* x   = (const float*)d_in[0];
    const float* gnw = (const float*)d_in[1];
    const float* gnb = (const float*)d_in[2];
    const float* fcw = (const float*)d_in[3];
    const float* fcb = (const float*)d_in[4];
    float* out = (float*)d_out;

    const int smem_bytes = SMEM_F * 4;        // 109376 B -> occ 2
    cudaFuncSetAttribute(fused_kernel,
                         cudaFuncAttributeMaxDynamicSharedMemorySize, smem_bytes);

    stats1<<<dim3(NB, NBANDS, NCH), 256>>>(x);
    stats2_prep<<<dim3(NBANDS, NB + 1), 256>>>(gnw, gnb, fcw, fcb);
    fused_kernel<<<dim3(NT / TT, NB, 2), 512, smem_bytes>>>(x, out);
}

// round 15
// speedup vs baseline: 1.4821x; 1.0097x over previous
#include <cuda_runtime.h>

#define NBANDS 31
#define NB     16
#define NT     1000
#define NF     257
#define NO     128
#define MAXC   34
#define KTOT   536      // sum of roundup4(2*bw)
#define TT     10       // time tile per block
#define YS     12       // y row stride (floats, 48B: keeps 16B alignment)
#define NCH    4        // stats chunks per (b,band)
#define OUTW   (NO * NBANDS)   // 3968
#define OHW    (64 * NBANDS)   // 1984 floats per (t, o-half)

__constant__ int c_bw[NBANDS] = {
    2,3,3,3,3,3,3,3,3,3,3,
    8,8,8,8,8,8,8,8,8,8,8,8,
    16,16,16,16,16,16,16,17
};
__constant__ int c_kal[NBANDS] = {
    0,4,12,20,28,36,44,52,60,68,76,
    84,100,116,132,148,164,180,196,212,228,244,260,
    276,308,340,372,404,436,468,500
};
__constant__ int c_f0[NBANDS] = {
    0,2,5,8,11,14,17,20,23,26,29,
    32,40,48,56,64,72,80,88,96,104,112,120,
    128,144,160,176,192,208,224,240
};
// 16 band-groups (one warp each); padded-C sums 32..44
__constant__ int c_gs[17] = {0,1,2,3,4,5,6,7,8,10,12,14,16,18,21,26,31};
__constant__ int c_gb[31] = {
    30,
    23,24,25,26,27,28,29,
    11,12, 13,14, 15,16, 17,18, 19,20,
    21,22,0,
    1,2,3,4,5,
    6,7,8,9,10
};
// k-slots that are zero-padding
__constant__ int c_pad[22] = {
    10,11,18,19,26,27,34,35,42,43,50,51,58,59,66,67,74,75,82,83,534,535
};

// static scratch
__device__ float  d_A2[NB * KTOT];
__device__ float  d_B2[NB * KTOT];
// per-half weights: [h][kslot][64], pos 2l+s holds o = h*64 + l + 32*s
__device__ float  d_w2h[2 * KTOT * 64];
// bias, same per-half pairing: [band][h][64]
__device__ float  d_bp[NBANDS * NO];
__device__ float2 d_ps[NB * NBANDS * NCH];    // partial (sum, sumsq)

__device__ __forceinline__ int kg_of_f(int f)
{
    if (f >= 32) return 2 * f + 20;
    if (f >= 2)  return 2 * f - 2 + 2 * ((f + 1) / 3);
    return 2 * f;
}

__device__ __forceinline__ float2 u2f(unsigned long long u)
{
    float2 r;
    asm("mov.b64 {%0,%1}, %2;" : "=f"(r.x), "=f"(r.y) : "l"(u));
    return r;
}
__device__ __forceinline__ unsigned long long dupf(float f)
{
    unsigned long long r;
    asm("mov.b64 %0, {%1, %1};" : "=l"(r) : "f"(f));
    return r;
}

// ---------------------------------------------------------------------------
// Kernel A: z < NCH -> stats partial sums (x4-unrolled float4, high MLP);
//           z == NCH && b == 0 -> weight/bias prep (overlaps with stats).
// ---------------------------------------------------------------------------
__global__ __launch_bounds__(256)
void stats1_prep(const float* __restrict__ x,
                 const float* __restrict__ fcw, const float* __restrict__ fcb)
{
    const int b    = blockIdx.x;
    const int band = blockIdx.y;
    const int ch   = blockIdx.z;
    const int bw   = c_bw[band];
    const int kal  = c_kal[band];

    if (ch == NCH) {
        if (b != 0) return;
        // per-half weight prep: d_w2h[h][kal+k][2l+s] = w[o = h*64+l+32s]
        const int C  = 2 * bw;
        const int kp = (C + 3) & ~3;
        for (int idx = threadIdx.x; idx < kp * NO; idx += 256) {
            const int k = idx >> 7;
            const int p = idx & 127;
            const int h = p >> 6;
            const int r = p & 63;
            const int l = r >> 1;
            const int s = r & 1;
            const int o = h * 64 + l + 32 * s;
            d_w2h[(h * KTOT + kal + k) * 64 + 2 * l + s] =
                (k < C) ? fcw[(band * NO + o) * MAXC + k] : 0.0f;
        }
        if (threadIdx.x < NO) {
            const int p = threadIdx.x;
            const int h = p >> 6;
            const int r = p & 63;
            const int l = r >> 1;
            const int s = r & 1;
            d_bp[band * NO + p] = fcb[band * NO + h * 64 + l + 32 * s];
        }
        return;
    }

    const float4* p = (const float4*)(x + (size_t)(b * NF + c_f0[band]) * (NT * 2));
    const int nv = bw * NT / 2;
    const int i0 = (int)((long long)nv * ch / NCH);
    const int i1 = (int)((long long)nv * (ch + 1) / NCH);

    float4 a1 = make_float4(0.f, 0.f, 0.f, 0.f);
    float4 a2 = a1;
    int i = i0 + threadIdx.x;
    // x4 unrolled: 4 independent loads in flight per thread
    for (; i + 768 < i1; i += 1024) {
        float4 v0 = p[i];
        float4 v1 = p[i + 256];
        float4 v2 = p[i + 512];
        float4 v3 = p[i + 768];
        a1.x += v0.x; a1.y += v0.y; a1.z += v0.z; a1.w += v0.w;
        a2.x = fmaf(v0.x, v0.x, a2.x); a2.y = fmaf(v0.y, v0.y, a2.y);
        a2.z = fmaf(v0.z, v0.z, a2.z); a2.w = fmaf(v0.w, v0.w, a2.w);
        a1.x += v1.x; a1.y += v1.y; a1.z += v1.z; a1.w += v1.w;
        a2.x = fmaf(v1.x, v1.x, a2.x); a2.y = fmaf(v1.y, v1.y, a2.y);
        a2.z = fmaf(v1.z, v1.z, a2.z); a2.w = fmaf(v1.w, v1.w, a2.w);
        a1.x += v2.x; a1.y += v2.y; a1.z += v2.z; a1.w += v2.w;
        a2.x = fmaf(v2.x, v2.x, a2.x); a2.y = fmaf(v2.y, v2.y, a2.y);
        a2.z = fmaf(v2.z, v2.z, a2.z); a2.w = fmaf(v2.w, v2.w, a2.w);
        a1.x += v3.x; a1.y += v3.y; a1.z += v3.z; a1.w += v3.w;
        a2.x = fmaf(v3.x, v3.x, a2.x); a2.y = fmaf(v3.y, v3.y, a2.y);
        a2.z = fmaf(v3.z, v3.z, a2.z); a2.w = fmaf(v3.w, v3.w, a2.w);
    }
    for (; i < i1; i += 256) {
        float4 v = p[i];
        a1.x += v.x; a1.y += v.y; a1.z += v.z; a1.w += v.w;
        a2.x = fmaf(v.x, v.x, a2.x); a2.y = fmaf(v.y, v.y, a2.y);
        a2.z = fmaf(v.z, v.z, a2.z); a2.w = fmaf(v.w, v.w, a2.w);
    }
    float s  = (a1.x + a1.y) + (a1.z + a1.w);
    float s2 = (a2.x + a2.y) + (a2.z + a2.w);
    for (int off = 16; off; off >>= 1) {
        s  += __shfl_down_sync(0xFFFFFFFFu, s,  off);
        s2 += __shfl_down_sync(0xFFFFFFFFu, s2, off);
    }
    __shared__ float sh0[8], sh1[8];
    const int w = threadIdx.x >> 5, l = threadIdx.x & 31;
    if (l == 0) { sh0[w] = s; sh1[w] = s2; }
    __syncthreads();
    if (threadIdx.x == 0) {
        float ts = 0.f, ts2 = 0.f;
        #pragma unroll
        for (int k = 0; k < 8; k++) { ts += sh0[k]; ts2 += sh1[k]; }
        d_ps[(b * NBANDS + band) * NCH + ch] = make_float2(ts, ts2);
    }
}

// ---------------------------------------------------------------------------
// Kernel B: stats finalize (deterministic fp64 combine), fold GN into A, B.
// ---------------------------------------------------------------------------
__global__ __launch_bounds__(64)
void stats2(const float* __restrict__ gnw, const float* __restrict__ gnb)
{
    const int b    = blockIdx.x;
    const int band = blockIdx.y;
    const int bw   = c_bw[band];
    const int n    = bw * NT * 2;

    __shared__ float sh_mean, sh_inv;
    if (threadIdx.x == 0) {
        double ts = 0.0, ts2 = 0.0;
        #pragma unroll
        for (int i = 0; i < NCH; i++) {
            float2 v = d_ps[(b * NBANDS + band) * NCH + i];
            ts += (double)v.x; ts2 += (double)v.y;
        }
        double mean = ts / n;
        double var  = ts2 / n - mean * mean;
        sh_mean = (float)mean;
        sh_inv  = rsqrtf((float)var + 1e-5f);
    }
    __syncthreads();
    const int c = 2 * bw;
    if (threadIdx.x < c) {
        float gw = gnw[band * MAXC + threadIdx.x];
        float gb = gnb[band * MAXC + threadIdx.x];
        float A  = gw * sh_inv;
        int   kg = c_kal[band] + threadIdx.x;
        d_A2[b * KTOT + kg] = A;
        d_B2[b * KTOT + kg] = gb - A * sh_mean;
    }
}

// ---------------------------------------------------------------------------
// Fused kernel (unchanged from R14 best): block = (10-t tile, batch, o-half),
// occ 2, t-pair f32x2 packing, depth-4 weight pipeline, conflict-free
// staging, 10 contiguous TMA bulk stores.
// ---------------------------------------------------------------------------
#define SOUT_F   (TT * OHW)                   // 19840 floats (79360 B)
#define SY_F     (KTOT * YS)                  // 6432 floats  (25728 B)
#define SMEM_F   (SOUT_F + SY_F + 2 * KTOT)   // 27344 floats = 109376 B

#define FMA2(acc, wv, yv) \
    asm("fma.rn.f32x2 %0, %1, %2, %0;" : "+l"(acc) : "l"(wv), "l"(yv));

__global__ __launch_bounds__(512, 2)
void fused_kernel(const float* __restrict__ x,
                  float* __restrict__ out)
{
    extern __shared__ float sm[];
    float* s_out = sm;                        // [t][OHW] exact output order
    float* s_y   = sm + SOUT_F;               // [k][YS] (10 valid floats/row)
    float* s_A   = sm + SOUT_F + SY_F;
    float* s_B   = s_A + KTOT;

    const int b    = blockIdx.y;
    const int t0   = blockIdx.x * TT;
    const int h    = blockIdx.z;              // o-half
    const int tid  = threadIdx.x;
    const int lane = tid & 31;
    const int warp = tid >> 5;                // band group

    const unsigned long long* wbase =
        (const unsigned long long*)d_w2h + (size_t)h * KTOT * 32;

    // --- prefetch first band's bias + first 4 weight rows (hidden by y-build)
    int bi          = c_gs[warp];
    const int biEnd = c_gs[warp + 1];
    int band = c_gb[bi];
    int kal  = c_kal[band];
    unsigned long long bz =
        *((const unsigned long long*)(d_bp + band * NO + h * 64) + lane);
    const unsigned long long* wp = wbase + kal * 32 + lane;
    unsigned long long wq0 = wp[0];
    unsigned long long wq1 = wp[32];
    unsigned long long wq2 = wp[64];
    unsigned long long wq3 = wp[96];

    for (int i = tid; i < KTOT; i += 512) {
        s_A[i] = d_A2[b * KTOT + i];
        s_B[i] = d_B2[b * KTOT + i];
    }
    // zero the 22 padded k-slots (first 10 floats of each row)
    if (tid < 220) {
        const int slot = c_pad[tid / 10];
        s_y[slot * YS + (tid % 10)] = 0.0f;
    }
    __syncthreads();

    // y-build: s_y[kg][t] = A*x + B; float4 covers (t,t+1)x(re,im) -> 2 STS.64
    for (int idx = tid; idx < NF * 5; idx += 512) {
        const int f = idx / 5;
        const int q = idx - 5 * f;            // t-pair q: t = t0+2q, t0+2q+1
        const float4 v = *(const float4*)(x + ((size_t)(b * NF + f) * NT + t0) * 2 + q * 4);
        const int kg = kg_of_f(f);
        const float A0 = s_A[kg], B0 = s_B[kg];
        const float A1 = s_A[kg + 1], B1 = s_B[kg + 1];
        *(float2*)&s_y[kg * YS + 2 * q] =
            make_float2(fmaf(A0, v.x, B0), fmaf(A0, v.z, B0));
        *(float2*)&s_y[(kg + 1) * YS + 2 * q] =
            make_float2(fmaf(A1, v.y, B1), fmaf(A1, v.w, B1));
    }
    __syncthreads();

    // --- band loop, depth-4 pipelined weight stream
    for (;;) {
        const int kcnt = (2 * c_bw[band] + 3) & ~3;
        const float* yb = s_y + kal * YS;

        unsigned long long acc[5][2];   // [t-pair][oA/oB]
        {
            float2 bf = u2f(bz);
            unsigned long long bA = dupf(bf.x), bB = dupf(bf.y);
            #pragma unroll
            for (int tp = 0; tp < 5; tp++) { acc[tp][0] = bA; acc[tp][1] = bB; }
        }

        #pragma unroll 4
        for (int k = 0; k < kcnt; k++) {
            const unsigned long long w = wq0;
            wq0 = wq1; wq1 = wq2; wq2 = wq3;
            const int kn = (k + 4 < kcnt) ? k + 4 : k;   // clamp (L1 hit on reload)
            wq3 = wp[kn * 32];

            float2 wf = u2f(w);
            const unsigned long long wA = dupf(wf.x);
            const unsigned long long wB = dupf(wf.y);

            // y row: 10 floats, 16B-aligned (YS=12) -> 2x LDS.128 + 1x LDS.64
            const ulonglong2 y01 = *(const ulonglong2*)(yb + k * YS);      // pairs 0,1
            const ulonglong2 y23 = *(const ulonglong2*)(yb + k * YS + 4);  // pairs 2,3
            const unsigned long long y4 =
                *(const unsigned long long*)(yb + k * YS + 8);             // pair 4
            FMA2(acc[0][0], wA, y01.x) FMA2(acc[0][1], wB, y01.x)
            FMA2(acc[1][0], wA, y01.y) FMA2(acc[1][1], wB, y01.y)
            FMA2(acc[2][0], wA, y23.x) FMA2(acc[2][1], wB, y23.x)
            FMA2(acc[3][0], wA, y23.y) FMA2(acc[3][1], wB, y23.y)
            FMA2(acc[4][0], wA, y4)    FMA2(acc[4][1], wB, y4)
        }

        // prefetch next band before staging stores
        const int curBand = band;
        const bool more = (++bi < biEnd);
        if (more) {
            band = c_gb[bi];
            kal  = c_kal[band];
            wp   = wbase + kal * 32 + lane;
            bz   = *((const unsigned long long*)(d_bp + band * NO + h * 64) + lane);
            wq0 = wp[0]; wq1 = wp[32]; wq2 = wp[64]; wq3 = wp[96];
        }

        // conflict-free staging: addr = 31*lane + band (+992 for o+32);
        // strides (OHW=1984, 992) are 0 mod 32
        #pragma unroll
        for (int tp = 0; tp < 5; tp++) {
            float* so = s_out + (2 * tp) * OHW + 31 * lane + curBand;
            float2 pa = u2f(acc[tp][0]);    // o = h*64 + lane,    t / t+1
            float2 pb = u2f(acc[tp][1]);    // o = h*64 + lane+32
            so[0]         = pa.x;
            so[OHW]       = pa.y;
            so[992]       = pb.x;
            so[OHW + 992] = pb.y;
        }
        if (!more) break;
    }
    __syncthreads();

    // per-t contiguous bulk copies: 7936 B each (o-half slab is contiguous)
    if (tid == 0) {
        unsigned int saddr;
        asm("{ .reg .u64 t; cvta.to.shared.u64 t, %1; cvt.u32.u64 %0, t; }"
            : "=r"(saddr) : "l"(s_out));
        asm volatile("fence.proxy.async.shared::cta;" ::: "memory");
        #pragma unroll
        for (int t = 0; t < TT; t++) {
            float* dst = out + (size_t)(b * NT + t0 + t) * OUTW + h * OHW;
            asm volatile("cp.async.bulk.global.shared::cta.bulk_group [%0], [%1], %2;"
                         :: "l"(dst), "r"(saddr + t * (OHW * 4)), "n"(OHW * 4)
                         : "memory");
        }
        asm volatile("cp.async.bulk.commit_group;" ::: "memory");
        asm volatile("cp.async.bulk.wait_group.read 0;" ::: "memory");
    }
}

// ---------------------------------------------------------------------------
extern "C" void kernel_launch(void* const* d_in, const int* in_sizes, int n_in,
                              void* d_out, int out_size)
{
    const float* x   = (const float*)d_in[0];
    const float* gnw = (const float*)d_in[1];
    const float* gnb = (const float*)d_in[2];
    const float* fcw = (const float*)d_in[3];
    const float* fcb = (const float*)d_in[4];
    float* out = (float*)d_out;

    const int smem_bytes = SMEM_F * 4;        // 109376 B -> occ 2
    cudaFuncSetAttribute(fused_kernel,
                         cudaFuncAttributeMaxDynamicSharedMemorySize, smem_bytes);

    stats1_prep<<<dim3(NB, NBANDS, NCH + 1), 256>>>(x, fcw, fcb);
    stats2<<<dim3(NB, NBANDS), 64>>>(gnw, gnb);
    fused_kernel<<<dim3(NT / TT, NB, 2), 512, smem_bytes>>>(x, out);
}

// round 16
// speedup vs baseline: 1.5820x; 1.0674x over previous
#include <cuda_runtime.h>

#define NBANDS 31
#define NB     16
#define NT     1000
#define NF     257
#define NO     128
#define MAXC   34
#define KTOT   536      // sum of roundup4(2*bw)
#define KTOT4  540      // + 4 overread rows for clamp-free prefetch
#define TT     10       // time tile per block
#define YS     12       // y row stride (floats, 48B: keeps 16B alignment)
#define NCH    4        // stats chunks per (b,band)
#define OUTW   (NO * NBANDS)   // 3968
#define OHW    (64 * NBANDS)   // 1984 floats per (t, o-half)

__constant__ int c_bw[NBANDS] = {
    2,3,3,3,3,3,3,3,3,3,3,
    8,8,8,8,8,8,8,8,8,8,8,8,
    16,16,16,16,16,16,16,17
};
__constant__ int c_kal[NBANDS] = {
    0,4,12,20,28,36,44,52,60,68,76,
    84,100,116,132,148,164,180,196,212,228,244,260,
    276,308,340,372,404,436,468,500
};
__constant__ int c_f0[NBANDS] = {
    0,2,5,8,11,14,17,20,23,26,29,
    32,40,48,56,64,72,80,88,96,104,112,120,
    128,144,160,176,192,208,224,240
};
// 16 band-groups rebalanced by cost = kcnt + 3 (prologue/staging):
// max 44 vs previous ~55
__constant__ int c_gs[17] = {0,1,3,5,7,8,9,10,11,13,15,17,19,21,23,27,31};
__constant__ int c_gb[31] = {
    30,
    23,0,  24,1,  25,2,
    26, 27, 28, 29,
    11,12, 13,14, 15,16, 17,18, 19,20, 21,22,
    3,4,5,6,
    7,8,9,10
};

// static scratch
__device__ float  d_A2[NB * KTOT];
__device__ float  d_B2[NB * KTOT];
// per-half weights: [h][kslot][64] with 4 overread rows; pos 2l+s holds
// o = h*64 + l + 32*s
__device__ float  d_w2h[2 * KTOT4 * 64];
// bias, same per-half pairing: [band][h][64]
__device__ float  d_bp[NBANDS * NO];
__device__ float2 d_ps[NB * NBANDS * NCH];    // partial (sum, sumsq)

__device__ __forceinline__ int kg_of_f(int f)
{
    if (f >= 32) return 2 * f + 20;
    if (f >= 2)  return 2 * f - 2 + 2 * ((f + 1) / 3);
    return 2 * f;
}

__device__ __forceinline__ float2 u2f(unsigned long long u)
{
    float2 r;
    asm("mov.b64 {%0,%1}, %2;" : "=f"(r.x), "=f"(r.y) : "l"(u));
    return r;
}
__device__ __forceinline__ unsigned long long dupf(float f)
{
    unsigned long long r;
    asm("mov.b64 %0, {%1, %1};" : "=l"(r) : "f"(f));
    return r;
}

// ---------------------------------------------------------------------------
// Kernel A: z < NCH -> stats partial sums (x4-unrolled float4, high MLP);
//           z == NCH && b == 0 -> weight/bias prep (overlaps with stats).
// ---------------------------------------------------------------------------
__global__ __launch_bounds__(256)
void stats1_prep(const float* __restrict__ x,
                 const float* __restrict__ fcw, const float* __restrict__ fcb)
{
    const int b    = blockIdx.x;
    const int band = blockIdx.y;
    const int ch   = blockIdx.z;
    const int bw   = c_bw[band];
    const int kal  = c_kal[band];

    if (ch == NCH) {
        if (b != 0) return;
        // per-half weight prep (exact C rows only — pads never read)
        const int C = 2 * bw;
        for (int idx = threadIdx.x; idx < C * NO; idx += 256) {
            const int k = idx >> 7;
            const int p = idx & 127;
            const int h = p >> 6;
            const int r = p & 63;
            const int l = r >> 1;
            const int s = r & 1;
            const int o = h * 64 + l + 32 * s;
            d_w2h[(h * KTOT4 + kal + k) * 64 + 2 * l + s] =
                fcw[(band * NO + o) * MAXC + k];
        }
        if (threadIdx.x < NO) {
            const int p = threadIdx.x;
            const int h = p >> 6;
            const int r = p & 63;
            const int l = r >> 1;
            const int s = r & 1;
            d_bp[band * NO + p] = fcb[band * NO + h * 64 + l + 32 * s];
        }
        return;
    }

    const float4* p = (const float4*)(x + (size_t)(b * NF + c_f0[band]) * (NT * 2));
    const int nv = bw * NT / 2;
    const int i0 = (int)((long long)nv * ch / NCH);
    const int i1 = (int)((long long)nv * (ch + 1) / NCH);

    float4 a1 = make_float4(0.f, 0.f, 0.f, 0.f);
    float4 a2 = a1;
    int i = i0 + threadIdx.x;
    for (; i + 768 < i1; i += 1024) {
        float4 v0 = p[i];
        float4 v1 = p[i + 256];
        float4 v2 = p[i + 512];
        float4 v3 = p[i + 768];
        a1.x += v0.x; a1.y += v0.y; a1.z += v0.z; a1.w += v0.w;
        a2.x = fmaf(v0.x, v0.x, a2.x); a2.y = fmaf(v0.y, v0.y, a2.y);
        a2.z = fmaf(v0.z, v0.z, a2.z); a2.w = fmaf(v0.w, v0.w, a2.w);
        a1.x += v1.x; a1.y += v1.y; a1.z += v1.z; a1.w += v1.w;
        a2.x = fmaf(v1.x, v1.x, a2.x); a2.y = fmaf(v1.y, v1.y, a2.y);
        a2.z = fmaf(v1.z, v1.z, a2.z); a2.w = fmaf(v1.w, v1.w, a2.w);
        a1.x += v2.x; a1.y += v2.y; a1.z += v2.z; a1.w += v2.w;
        a2.x = fmaf(v2.x, v2.x, a2.x); a2.y = fmaf(v2.y, v2.y, a2.y);
        a2.z = fmaf(v2.z, v2.z, a2.z); a2.w = fmaf(v2.w, v2.w, a2.w);
        a1.x += v3.x; a1.y += v3.y; a1.z += v3.z; a1.w += v3.w;
        a2.x = fmaf(v3.x, v3.x, a2.x); a2.y = fmaf(v3.y, v3.y, a2.y);
        a2.z = fmaf(v3.z, v3.z, a2.z); a2.w = fmaf(v3.w, v3.w, a2.w);
    }
    for (; i < i1; i += 256) {
        float4 v = p[i];
        a1.x += v.x; a1.y += v.y; a1.z += v.z; a1.w += v.w;
        a2.x = fmaf(v.x, v.x, a2.x); a2.y = fmaf(v.y, v.y, a2.y);
        a2.z = fmaf(v.z, v.z, a2.z); a2.w = fmaf(v.w, v.w, a2.w);
    }
    float s  = (a1.x + a1.y) + (a1.z + a1.w);
    float s2 = (a2.x + a2.y) + (a2.z + a2.w);
    for (int off = 16; off; off >>= 1) {
        s  += __shfl_down_sync(0xFFFFFFFFu, s,  off);
        s2 += __shfl_down_sync(0xFFFFFFFFu, s2, off);
    }
    __shared__ float sh0[8], sh1[8];
    const int w = threadIdx.x >> 5, l = threadIdx.x & 31;
    if (l == 0) { sh0[w] = s; sh1[w] = s2; }
    __syncthreads();
    if (threadIdx.x == 0) {
        float ts = 0.f, ts2 = 0.f;
        #pragma unroll
        for (int k = 0; k < 8; k++) { ts += sh0[k]; ts2 += sh1[k]; }
        d_ps[(b * NBANDS + band) * NCH + ch] = make_float2(ts, ts2);
    }
}

// ---------------------------------------------------------------------------
// Kernel B: stats finalize (deterministic fp64 combine), fold GN into A, B.
// ---------------------------------------------------------------------------
__global__ __launch_bounds__(64)
void stats2(const float* __restrict__ gnw, const float* __restrict__ gnb)
{
    const int b    = blockIdx.x;
    const int band = blockIdx.y;
    const int bw   = c_bw[band];
    const int n    = bw * NT * 2;

    __shared__ float sh_mean, sh_inv;
    if (threadIdx.x == 0) {
        double ts = 0.0, ts2 = 0.0;
        #pragma unroll
        for (int i = 0; i < NCH; i++) {
            float2 v = d_ps[(b * NBANDS + band) * NCH + i];
            ts += (double)v.x; ts2 += (double)v.y;
        }
        double mean = ts / n;
        double var  = ts2 / n - mean * mean;
        sh_mean = (float)mean;
        sh_inv  = rsqrtf((float)var + 1e-5f);
    }
    __syncthreads();
    const int c = 2 * bw;
    if (threadIdx.x < c) {
        float gw = gnw[band * MAXC + threadIdx.x];
        float gb = gnb[band * MAXC + threadIdx.x];
        float A  = gw * sh_inv;
        int   kg = c_kal[band] + threadIdx.x;
        d_A2[b * KTOT + kg] = A;
        d_B2[b * KTOT + kg] = gb - A * sh_mean;
    }
}

// ---------------------------------------------------------------------------
// Fused kernel: block = (10-t tile, batch, o-half), occ 2. Exact k-count
// (no pad iterations), clamp-free depth-4 weight pipeline (overread rows),
// t-pair f32x2 packing, conflict-free staging, 10 contiguous bulk stores.
// ---------------------------------------------------------------------------
#define SOUT_F   (TT * OHW)                   // 19840 floats (79360 B)
#define SY_F     (KTOT * YS)                  // 6432 floats  (25728 B)
#define SMEM_F   (SOUT_F + SY_F + 2 * KTOT)   // 27344 floats = 109376 B

#define FMA2(acc, wv, yv) \
    asm("fma.rn.f32x2 %0, %1, %2, %0;" : "+l"(acc) : "l"(wv), "l"(yv));

__global__ __launch_bounds__(512, 2)
void fused_kernel(const float* __restrict__ x,
                  float* __restrict__ out)
{
    extern __shared__ float sm[];
    float* s_out = sm;                        // [t][OHW] exact output order
    float* s_y   = sm + SOUT_F;               // [k][YS] (10 valid floats/row)
    float* s_A   = sm + SOUT_F + SY_F;
    float* s_B   = s_A + KTOT;

    const int b    = blockIdx.y;
    const int t0   = blockIdx.x * TT;
    const int h    = blockIdx.z;              // o-half
    const int tid  = threadIdx.x;
    const int lane = tid & 31;
    const int warp = tid >> 5;                // band group

    const unsigned long long* wbase =
        (const unsigned long long*)d_w2h + (size_t)h * KTOT4 * 32;

    // --- prefetch first band's bias + first 4 weight rows (hidden by y-build)
    int bi          = c_gs[warp];
    const int biEnd = c_gs[warp + 1];
    int band = c_gb[bi];
    int kal  = c_kal[band];
    unsigned long long bz =
        *((const unsigned long long*)(d_bp + band * NO + h * 64) + lane);
    const unsigned long long* wp = wbase + kal * 32 + lane;
    unsigned long long wq0 = wp[0];
    unsigned long long wq1 = wp[32];
    unsigned long long wq2 = wp[64];
    unsigned long long wq3 = wp[96];

    for (int i = tid; i < KTOT; i += 512) {
        s_A[i] = d_A2[b * KTOT + i];
        s_B[i] = d_B2[b * KTOT + i];
    }
    __syncthreads();

    // y-build: s_y[kg][t] = A*x + B; float4 covers (t,t+1)x(re,im) -> 2 STS.64
    for (int idx = tid; idx < NF * 5; idx += 512) {
        const int f = idx / 5;
        const int q = idx - 5 * f;            // t-pair q: t = t0+2q, t0+2q+1
        const float4 v = *(const float4*)(x + ((size_t)(b * NF + f) * NT + t0) * 2 + q * 4);
        const int kg = kg_of_f(f);
        const float A0 = s_A[kg], B0 = s_B[kg];
        const float A1 = s_A[kg + 1], B1 = s_B[kg + 1];
        *(float2*)&s_y[kg * YS + 2 * q] =
            make_float2(fmaf(A0, v.x, B0), fmaf(A0, v.z, B0));
        *(float2*)&s_y[(kg + 1) * YS + 2 * q] =
            make_float2(fmaf(A1, v.y, B1), fmaf(A1, v.w, B1));
    }
    __syncthreads();

    // --- band loop, exact k-count, clamp-free depth-4 weight pipeline
    for (;;) {
        const int kcnt = 2 * c_bw[band];      // exact (even), no pad iters
        const float* yb = s_y + kal * YS;

        unsigned long long acc[5][2];   // [t-pair][oA/oB]
        {
            float2 bf = u2f(bz);
            unsigned long long bA = dupf(bf.x), bB = dupf(bf.y);
            #pragma unroll
            for (int tp = 0; tp < 5; tp++) { acc[tp][0] = bA; acc[tp][1] = bB; }
        }

        #pragma unroll 4
        for (int k = 0; k < kcnt; k++) {
            const unsigned long long w = wq0;
            wq0 = wq1; wq1 = wq2; wq2 = wq3;
            wq3 = wp[(k + 4) * 32];           // overread OK (4 spare rows)

            float2 wf = u2f(w);
            const unsigned long long wA = dupf(wf.x);
            const unsigned long long wB = dupf(wf.y);

            // y row: 10 floats, 16B-aligned (YS=12) -> 2x LDS.128 + 1x LDS.64
            const ulonglong2 y01 = *(const ulonglong2*)(yb + k * YS);      // pairs 0,1
            const ulonglong2 y23 = *(const ulonglong2*)(yb + k * YS + 4);  // pairs 2,3
            const unsigned long long y4 =
                *(const unsigned long long*)(yb + k * YS + 8);             // pair 4
            FMA2(acc[0][0], wA, y01.x) FMA2(acc[0][1], wB, y01.x)
            FMA2(acc[1][0], wA, y01.y) FMA2(acc[1][1], wB, y01.y)
            FMA2(acc[2][0], wA, y23.x) FMA2(acc[2][1], wB, y23.x)
            FMA2(acc[3][0], wA, y23.y) FMA2(acc[3][1], wB, y23.y)
            FMA2(acc[4][0], wA, y4)    FMA2(acc[4][1], wB, y4)
        }

        // prefetch next band before staging stores
        const int curBand = band;
        const bool more = (++bi < biEnd);
        if (more) {
            band = c_gb[bi];
            kal  = c_kal[band];
            wp   = wbase + kal * 32 + lane;
            bz   = *((const unsigned long long*)(d_bp + band * NO + h * 64) + lane);
            wq0 = wp[0]; wq1 = wp[32]; wq2 = wp[64]; wq3 = wp[96];
        }

        // conflict-free staging: addr = 31*lane + band (+992 for o+32);
        // strides (OHW=1984, 992) are 0 mod 32
        #pragma unroll
        for (int tp = 0; tp < 5; tp++) {
            float* so = s_out + (2 * tp) * OHW + 31 * lane + curBand;
            float2 pa = u2f(acc[tp][0]);    // o = h*64 + lane,    t / t+1
            float2 pb = u2f(acc[tp][1]);    // o = h*64 + lane+32
            so[0]         = pa.x;
            so[OHW]       = pa.y;
            so[992]       = pb.x;
            so[OHW + 992] = pb.y;
        }
        if (!more) break;
    }
    __syncthreads();

    // per-t contiguous bulk copies: 7936 B each (o-half slab is contiguous)
    if (tid == 0) {
        unsigned int saddr;
        asm("{ .reg .u64 t; cvta.to.shared.u64 t, %1; cvt.u32.u64 %0, t; }"
            : "=r"(saddr) : "l"(s_out));
        asm volatile("fence.proxy.async.shared::cta;" ::: "memory");
        #pragma unroll
        for (int t = 0; t < TT; t++) {
            float* dst = out + (size_t)(b * NT + t0 + t) * OUTW + h * OHW;
            asm volatile("cp.async.bulk.global.shared::cta.bulk_group [%0], [%1], %2;"
                         :: "l"(dst), "r"(saddr + t * (OHW * 4)), "n"(OHW * 4)
                         : "memory");
        }
        asm volatile("cp.async.bulk.commit_group;" ::: "memory");
        asm volatile("cp.async.bulk.wait_group.read 0;" ::: "memory");
    }
}

// ---------------------------------------------------------------------------
extern "C" void kernel_launch(void* const* d_in, const int* in_sizes, int n_in,
                              void* d_out, int out_size)
{
    const float* x   = (const float*)d_in[0];
    const float* gnw = (const float*)d_in[1];
    const float* gnb = (const float*)d_in[2];
    const float* fcw = (const float*)d_in[3];
    const float* fcb = (const float*)d_in[4];
    float* out = (float*)d_out;

    const int smem_bytes = SMEM_F * 4;        // 109376 B -> occ 2
    cudaFuncSetAttribute(fused_kernel,
                         cudaFuncAttributeMaxDynamicSharedMemorySize, smem_bytes);

    stats1_prep<<<dim3(NB, NBANDS, NCH + 1), 256>>>(x, fcw, fcb);
    stats2<<<dim3(NB, NBANDS), 64>>>(gnw, gnb);
    fused_kernel<<<dim3(NT / TT, NB, 2), 512, smem_bytes>>>(x, out);
}